// round 7
// baseline (speedup 1.0000x reference)
#include <cuda_runtime.h>
#include <cuda_bf16.h>
#include <cstdint>

#define BB 8
#define SS 2048
#define DD 512
#define UU 512
#define QT2 64
#define NT2 (SS/QT2)
#define WIN2 320
#define SCALE 0.044194173824159216f

// ---------------------------------------------------------------------------
// Scratch
// ---------------------------------------------------------------------------
__device__ __nv_bfloat16 g_xhi[(size_t)BB * SS * DD];
__device__ __nv_bfloat16 g_xlo[(size_t)BB * SS * DD];
__device__ __nv_bfloat16 g_wthi[3ull * UU * DD];
__device__ __nv_bfloat16 g_wtlo[3ull * UU * DD];
__device__ __nv_bfloat16 g_qh[(size_t)BB * SS * UU];
__device__ __nv_bfloat16 g_ql[(size_t)BB * SS * UU];
__device__ __nv_bfloat16 g_kh[(size_t)BB * SS * UU];
__device__ __nv_bfloat16 g_kl[(size_t)BB * SS * UU];
__device__ __nv_bfloat16 g_vh[(size_t)BB * SS * UU];
__device__ __nv_bfloat16 g_vl[(size_t)BB * SS * UU];

// ---------------------------------------------------------------------------
// Helpers (baseline PTX only — valid under compute_103)
// ---------------------------------------------------------------------------
__device__ __forceinline__ uint32_t smem_u32(const void* p) {
    uint32_t a;
    asm("{ .reg .u64 t; cvta.to.shared.u64 t, %1; cvt.u32.u64 %0, t; }"
        : "=r"(a) : "l"(p));
    return a;
}
#define SWZ(o) ((o) ^ (((o) >> 3) & 0x70))

__device__ __forceinline__ void cp16(uint32_t s, const void* g) {
    asm volatile("cp.async.cg.shared.global [%0], [%1], 16;" :: "r"(s), "l"(g));
}
#define CP_COMMIT() asm volatile("cp.async.commit_group;" ::: "memory")
#define CP_WAIT(n)  asm volatile("cp.async.wait_group %0;" :: "n"(n) : "memory")

__device__ __forceinline__ void ldm_x4(uint32_t* r, uint32_t a) {
    asm volatile("ldmatrix.sync.aligned.m8n8.x4.shared.b16 {%0,%1,%2,%3}, [%4];"
        : "=r"(r[0]), "=r"(r[1]), "=r"(r[2]), "=r"(r[3]) : "r"(a));
}
__device__ __forceinline__ void ldm_x4t(uint32_t* r, uint32_t a) {
    asm volatile("ldmatrix.sync.aligned.m8n8.x4.trans.shared.b16 {%0,%1,%2,%3}, [%4];"
        : "=r"(r[0]), "=r"(r[1]), "=r"(r[2]), "=r"(r[3]) : "r"(a));
}
__device__ __forceinline__ void mma_bf16(float* d, const uint32_t* a, const uint32_t* b) {
    asm volatile("mma.sync.aligned.m16n8k16.row.col.f32.bf16.bf16.f32 "
        "{%0,%1,%2,%3}, {%4,%5,%6,%7}, {%8,%9}, {%0,%1,%2,%3};"
        : "+f"(d[0]), "+f"(d[1]), "+f"(d[2]), "+f"(d[3])
        : "r"(a[0]), "r"(a[1]), "r"(a[2]), "r"(a[3]), "r"(b[0]), "r"(b[1]));
}
__device__ __forceinline__ int iclamp(int v, int lo, int hi) {
    return v < lo ? lo : (v > hi ? hi : v);
}

// ---------------------------------------------------------------------------
// Prep: fp32 -> bf16 hi/lo split of X
// ---------------------------------------------------------------------------
__global__ __launch_bounds__(256) void prep_x(const float* __restrict__ x)
{
    const size_t i4 = (size_t)blockIdx.x * 256 + threadIdx.x;
    float4 v = ((const float4*)x)[i4];
    __nv_bfloat16 h0 = __float2bfloat16(v.x), h1 = __float2bfloat16(v.y);
    __nv_bfloat16 h2 = __float2bfloat16(v.z), h3 = __float2bfloat16(v.w);
    __nv_bfloat162* oh = (__nv_bfloat162*)g_xhi;
    __nv_bfloat162* ol = (__nv_bfloat162*)g_xlo;
    oh[i4 * 2]     = __nv_bfloat162(h0, h1);
    oh[i4 * 2 + 1] = __nv_bfloat162(h2, h3);
    ol[i4 * 2]     = __nv_bfloat162(__float2bfloat16(v.x - __bfloat162float(h0)),
                                    __float2bfloat16(v.y - __bfloat162float(h1)));
    ol[i4 * 2 + 1] = __nv_bfloat162(__float2bfloat16(v.z - __bfloat162float(h2)),
                                    __float2bfloat16(v.w - __bfloat162float(h3)));
}

// ---------------------------------------------------------------------------
// Prep: transpose W[k][n] -> Wt[n][k], bf16 hi/lo
// ---------------------------------------------------------------------------
__global__ __launch_bounds__(256) void prep_w(
    const float* __restrict__ Wq, const float* __restrict__ Wk, const float* __restrict__ Wv)
{
    __shared__ float t[32][33];
    const int w = blockIdx.z;
    const float* __restrict__ W = (w == 0) ? Wq : (w == 1) ? Wk : Wv;
    const int n0 = blockIdx.x * 32;
    const int k0 = blockIdx.y * 32;
    const int tx = threadIdx.x & 31;
    const int ty = threadIdx.x >> 5;
#pragma unroll
    for (int i = 0; i < 4; i++) {
        const int r = ty + i * 8;
        t[r][tx] = W[(size_t)(k0 + r) * UU + n0 + tx];
    }
    __syncthreads();
    const size_t base = (size_t)w * UU * DD;
#pragma unroll
    for (int i = 0; i < 4; i++) {
        const int r = ty + i * 8;
        const float v = t[tx][r];
        __nv_bfloat16 h = __float2bfloat16(v);
        g_wthi[base + (size_t)(n0 + r) * DD + k0 + tx] = h;
        g_wtlo[base + (size_t)(n0 + r) * DD + k0 + tx] =
            __float2bfloat16(v - __bfloat162float(h));
    }
}

// ---------------------------------------------------------------------------
// QKV GEMM: CTA 128x128, 16 warps of 32x32 tiles, K=512 in 8 chunks of 64.
// 3-pass hi/lo bf16 mma, 2-stage cp.async double buffer, 512 threads.
// grid: (4, 128, 3), 128 KB smem.
// ---------------------------------------------------------------------------
#define Q_AH 0
#define Q_AL 16384
#define Q_BH 32768
#define Q_BL 49152
#define Q_BUF 65536
#define GEMM_SMEM (2 * Q_BUF)

__global__ __launch_bounds__(512, 1) void qkv_tc(
    const float* __restrict__ bq, const float* __restrict__ bk, const float* __restrict__ bv)
{
    extern __shared__ char sm[];
    const uint32_t sbase = smem_u32(sm);
    const int tid  = threadIdx.x;
    const int warp = tid >> 5;
    const int lane = tid & 31;
    const int w3 = blockIdx.z;
    const int n0 = blockIdx.x * 128;
    const int m0 = blockIdx.y * 128;

    const int wm = (warp & 3) * 32;
    const int wn = (warp >> 2) * 32;

    const __nv_bfloat16* __restrict__ xh = g_xhi + (size_t)m0 * DD;
    const __nv_bfloat16* __restrict__ xl = g_xlo + (size_t)m0 * DD;
    const __nv_bfloat16* __restrict__ wh = g_wthi + (size_t)w3 * UU * DD + (size_t)n0 * DD;
    const __nv_bfloat16* __restrict__ wl = g_wtlo + (size_t)w3 * UU * DD + (size_t)n0 * DD;

    auto issue_chunk = [&](int c, int buf) {
        const int kc0 = c * 64;
        const uint32_t bs = sbase + buf * Q_BUF;
#pragma unroll
        for (int i = 0; i < 2; i++) {
            const int f = tid + i * 512;
            const int row = f >> 3, seg = (f & 7) * 16;
            const uint32_t so = SWZ(row * 128 + seg);
            cp16(bs + Q_AH + so, (const char*)(xh + (size_t)row * DD + kc0) + seg);
            cp16(bs + Q_AL + so, (const char*)(xl + (size_t)row * DD + kc0) + seg);
            cp16(bs + Q_BH + so, (const char*)(wh + (size_t)row * DD + kc0) + seg);
            cp16(bs + Q_BL + so, (const char*)(wl + (size_t)row * DD + kc0) + seg);
        }
        CP_COMMIT();
    };

    float acc[2][4][4];
#pragma unroll
    for (int mt = 0; mt < 2; mt++)
#pragma unroll
        for (int nt = 0; nt < 4; nt++)
#pragma unroll
            for (int i = 0; i < 4; i++) acc[mt][nt][i] = 0.f;

    issue_chunk(0, 0);

    const int lsub = lane >> 3;
    const int lrow = lane & 7;
    const int a_ro = (lsub & 1) * 8;
    const int a_ko = (lsub >> 1) * 16;
    const int b_ro = (lsub >> 1) * 8;
    const int b_ko = (lsub & 1) * 16;

    for (int c = 0; c < 8; c++) {
        if (c < 7) { issue_chunk(c + 1, (c + 1) & 1); CP_WAIT(1); }
        else       { CP_WAIT(0); }
        __syncthreads();

        const uint32_t bs = sbase + (c & 1) * Q_BUF;

#pragma unroll
        for (int ks = 0; ks < 4; ks++) {
            const int kb = ks * 32;
            uint32_t ah[2][4], al[2][4];
#pragma unroll
            for (int mt = 0; mt < 2; mt++) {
                const uint32_t off = SWZ((wm + mt * 16 + lrow + a_ro) * 128 + kb + a_ko);
                ldm_x4(ah[mt], bs + Q_AH + off);
                ldm_x4(al[mt], bs + Q_AL + off);
            }
#pragma unroll
            for (int ntp = 0; ntp < 2; ntp++) {
                const uint32_t off = SWZ((wn + ntp * 16 + b_ro + lrow) * 128 + kb + b_ko);
                uint32_t bh[4], bl[4];
                ldm_x4(bh, bs + Q_BH + off);
                ldm_x4(bl, bs + Q_BL + off);
#pragma unroll
                for (int t = 0; t < 2; t++) {
#pragma unroll
                    for (int mt = 0; mt < 2; mt++) {
                        mma_bf16(acc[mt][ntp * 2 + t], ah[mt], bh + t * 2);
                        mma_bf16(acc[mt][ntp * 2 + t], ah[mt], bl + t * 2);
                        mma_bf16(acc[mt][ntp * 2 + t], al[mt], bh + t * 2);
                    }
                }
            }
        }
        __syncthreads();
    }

    // Epilogue: +bias, hi/lo split, store bf16
    const float* __restrict__ bias = (w3 == 0) ? bq : (w3 == 1) ? bk : bv;
    __nv_bfloat16* __restrict__ oh = (w3 == 0) ? g_qh : (w3 == 1) ? g_kh : g_vh;
    __nv_bfloat16* __restrict__ ol = (w3 == 0) ? g_ql : (w3 == 1) ? g_kl : g_vl;
    const int grp = lane >> 2;
    const int qd  = lane & 3;
#pragma unroll
    for (int nt = 0; nt < 4; nt++) {
        const int col = n0 + wn + nt * 8 + qd * 2;
        const float b0 = bias[col], b1 = bias[col + 1];
#pragma unroll
        for (int mt = 0; mt < 2; mt++) {
            const int r0 = m0 + wm + mt * 16 + grp;
            const float f0 = acc[mt][nt][0] + b0, f1 = acc[mt][nt][1] + b1;
            const float f2 = acc[mt][nt][2] + b0, f3 = acc[mt][nt][3] + b1;
            __nv_bfloat16 h0 = __float2bfloat16(f0), h1 = __float2bfloat16(f1);
            __nv_bfloat16 h2 = __float2bfloat16(f2), h3 = __float2bfloat16(f3);
            *(__nv_bfloat162*)&oh[(size_t)r0 * UU + col] = __nv_bfloat162(h0, h1);
            *(__nv_bfloat162*)&ol[(size_t)r0 * UU + col] = __nv_bfloat162(
                __float2bfloat16(f0 - __bfloat162float(h0)),
                __float2bfloat16(f1 - __bfloat162float(h1)));
            *(__nv_bfloat162*)&oh[(size_t)(r0 + 8) * UU + col] = __nv_bfloat162(h2, h3);
            *(__nv_bfloat162*)&ol[(size_t)(r0 + 8) * UU + col] = __nv_bfloat162(
                __float2bfloat16(f2 - __bfloat162float(h2)),
                __float2bfloat16(f3 - __bfloat162float(h3)));
        }
    }
}

// ---------------------------------------------------------------------------
// Fused attention, 512 threads: scores (4x4 warps of 16x80) + softmax
// (4 rows/warp) + P V (4x4 warps of 16x32 per 128-d chunk). 225 KB smem.
// ---------------------------------------------------------------------------
#define FA_AH 0
#define FA_AL 8192
#define FA_BH 16384
#define FA_BL 57344
#define FA_BUF 98304
#define SSTR 321
#define P_OFF 82944
#define V_OFF 164864
#define FA_SMEM 230400

__global__ __launch_bounds__(512, 1) void attn_fused(float* __restrict__ out)
{
    extern __shared__ char sm[];
    const uint32_t sbase = smem_u32(sm);
    const int tid  = threadIdx.x;
    const int warp = tid >> 5;
    const int lane = tid & 31;
    const int b  = blockIdx.y;
    const int q0 = blockIdx.x * QT2;
    const int kstart = q0 - 128;

    const __nv_bfloat16* __restrict__ qh = g_qh + (size_t)(b * SS + q0) * UU;
    const __nv_bfloat16* __restrict__ ql = g_ql + (size_t)(b * SS + q0) * UU;
    const __nv_bfloat16* __restrict__ kh = g_kh + (size_t)b * SS * UU;
    const __nv_bfloat16* __restrict__ kl = g_kl + (size_t)b * SS * UU;
    const __nv_bfloat16* __restrict__ vh = g_vh + (size_t)b * SS * UU;
    const __nv_bfloat16* __restrict__ vl = g_vl + (size_t)b * SS * UU;

    const int lsub = lane >> 3;
    const int lrow = lane & 7;
    const int a_ro = (lsub & 1) * 8;
    const int a_ko = (lsub >> 1) * 16;
    const int b_ro = (lsub >> 1) * 8;
    const int b_ko = (lsub & 1) * 16;

    const int wm = (warp & 3) * 16;      // M offset (phase 1 & 2)
    const int wn = (warp >> 2) * 80;     // N offset (phase 1)

    // ---------------- Phase 1: S = Q K^T ----------------
    auto issueK = [&](int c, int buf) {
        const int kc0 = c * 64;
        const uint32_t bs = sbase + buf * FA_BUF;
        {
            const int f = tid;               // 512 chunks of A (hi+lo)
            const int row = f >> 3, seg = (f & 7) * 16;
            const uint32_t so = SWZ(row * 128 + seg);
            cp16(bs + FA_AH + so, (const char*)(qh + (size_t)row * UU + kc0) + seg);
            cp16(bs + FA_AL + so, (const char*)(ql + (size_t)row * UU + kc0) + seg);
        }
#pragma unroll
        for (int i = 0; i < 5; i++) {        // 2560 chunks of K (hi+lo)
            const int f = tid + i * 512;
            const int row = f >> 3, seg = (f & 7) * 16;
            const int j = iclamp(kstart + row, 0, SS - 1);
            const uint32_t so = SWZ(row * 128 + seg);
            cp16(bs + FA_BH + so, (const char*)(kh + (size_t)j * UU + kc0) + seg);
            cp16(bs + FA_BL + so, (const char*)(kl + (size_t)j * UU + kc0) + seg);
        }
        CP_COMMIT();
    };

    float acc[10][4];
#pragma unroll
    for (int nt = 0; nt < 10; nt++)
#pragma unroll
        for (int i = 0; i < 4; i++) acc[nt][i] = 0.f;

    issueK(0, 0);

    for (int c = 0; c < 8; c++) {
        if (c < 7) { issueK(c + 1, (c + 1) & 1); CP_WAIT(1); }
        else       { CP_WAIT(0); }
        __syncthreads();

        const uint32_t bs = sbase + (c & 1) * FA_BUF;
#pragma unroll
        for (int ks = 0; ks < 4; ks++) {
            const int kb = ks * 32;
            uint32_t ah[4], al[4];
            {
                const uint32_t off = SWZ((wm + lrow + a_ro) * 128 + kb + a_ko);
                ldm_x4(ah, bs + FA_AH + off);
                ldm_x4(al, bs + FA_AL + off);
            }
#pragma unroll
            for (int ntp = 0; ntp < 5; ntp++) {
                const uint32_t off = SWZ((wn + ntp * 16 + b_ro + lrow) * 128 + kb + b_ko);
                uint32_t bh[4], bl[4];
                ldm_x4(bh, bs + FA_BH + off);
                ldm_x4(bl, bs + FA_BL + off);
#pragma unroll
                for (int t = 0; t < 2; t++) {
                    mma_bf16(acc[ntp * 2 + t], ah, bh + t * 2);
                    mma_bf16(acc[ntp * 2 + t], ah, bl + t * 2);
                    mma_bf16(acc[ntp * 2 + t], al, bh + t * 2);
                }
            }
        }
        __syncthreads();
    }

    // ---------------- V prefetch (overlaps softmax) ----------------
    auto issueV = [&](int dc, int kc, int vbuf) {
        const uint32_t bs = sbase + V_OFF + vbuf * 32768;
        const int d0 = dc * 128;
        {
            const int f = tid;               // 512 chunks per array
            const int row = f >> 3, seg = (f & 7) * 16;
            const int j = iclamp(kstart + kc * 64 + row, 0, SS - 1);
            const uint32_t so = SWZ(row * 128 + seg);
            cp16(bs + 0     + so, (const char*)(vh + (size_t)j * UU + d0) + seg);
            cp16(bs + 8192  + so, (const char*)(vl + (size_t)j * UU + d0) + seg);
            cp16(bs + 16384 + so, (const char*)(vh + (size_t)j * UU + d0 + 64) + seg);
            cp16(bs + 24576 + so, (const char*)(vl + (size_t)j * UU + d0 + 64) + seg);
        }
        CP_COMMIT();
    };
    issueV(0, 0, 0);

    // ---------------- S -> smem, masked softmax, P -> smem ----------------
    float* Ss = (float*)sm;
    const int grp = lane >> 2;
    const int qd  = lane & 3;
    {
        const int r0 = wm + grp;
#pragma unroll
        for (int nt = 0; nt < 10; nt++) {
            const int col = wn + nt * 8 + qd * 2;
            Ss[r0 * SSTR + col]           = acc[nt][0] * SCALE;
            Ss[r0 * SSTR + col + 1]       = acc[nt][1] * SCALE;
            Ss[(r0 + 8) * SSTR + col]     = acc[nt][2] * SCALE;
            Ss[(r0 + 8) * SSTR + col + 1] = acc[nt][3] * SCALE;
        }
    }
    __syncthreads();

#pragma unroll
    for (int r8 = 0; r8 < 4; r8++) {
        const int rr = warp * 4 + r8;
        const int cmin = (rr > -kstart) ? rr : -kstart;
        int cmax = rr + 256;
        const int chi = SS - 1 - kstart;
        if (chi < cmax) cmax = chi;

        float mx = -1e30f;
        for (int c = lane; c < WIN2; c += 32)
            if (c >= cmin && c <= cmax) mx = fmaxf(mx, Ss[rr * SSTR + c]);
#pragma unroll
        for (int off = 16; off > 0; off >>= 1)
            mx = fmaxf(mx, __shfl_xor_sync(0xFFFFFFFFu, mx, off));

        float sum = 0.f;
        for (int c = lane; c < WIN2; c += 32) {
            float e = 0.f;
            if (c >= cmin && c <= cmax) e = __expf(Ss[rr * SSTR + c] - mx);
            Ss[rr * SSTR + c] = e;
            sum += e;
        }
#pragma unroll
        for (int off = 16; off > 0; off >>= 1)
            sum += __shfl_xor_sync(0xFFFFFFFFu, sum, off);

        const float inv = 1.0f / sum;
        for (int c = lane; c < WIN2; c += 32) {
            const float p = Ss[rr * SSTR + c] * inv;
            const __nv_bfloat16 h = __float2bfloat16(p);
            const uint32_t pb = P_OFF + (c >> 6) * 16384 + SWZ(rr * 128 + (c & 63) * 2);
            *(__nv_bfloat16*)(sm + pb)        = h;
            *(__nv_bfloat16*)(sm + pb + 8192) = __float2bfloat16(p - __bfloat162float(h));
        }
    }
    __syncthreads();

    // ---------------- Phase 2: out = P V ----------------
    const int wn2  = (warp >> 2) * 32;
    const int sub  = wn2 >> 6;
    const int nloc = wn2 & 63;

    for (int dc = 0; dc < 4; dc++) {
        float acc2[4][4];
#pragma unroll
        for (int nt = 0; nt < 4; nt++)
#pragma unroll
            for (int i = 0; i < 4; i++) acc2[nt][i] = 0.f;

        for (int kc = 0; kc < 5; kc++) {
            const int it = dc * 5 + kc;
            if (it < 19) {
                const int nit = it + 1;
                issueV(nit / 5, nit % 5, nit & 1);
                CP_WAIT(1);
            } else {
                CP_WAIT(0);
            }
            __syncthreads();

            const uint32_t vb = sbase + V_OFF + (it & 1) * 32768;
            const uint32_t Vh = vb + sub * 16384;
            const uint32_t Vl = Vh + 8192;
            const uint32_t Ph = sbase + P_OFF + kc * 16384;
            const uint32_t Pl = Ph + 8192;

#pragma unroll
            for (int ks = 0; ks < 4; ks++) {
                uint32_t ah[4], al[4];
                {
                    const uint32_t off = SWZ((wm + lrow + a_ro) * 128 + ks * 32 + a_ko);
                    ldm_x4(ah, Ph + off);
                    ldm_x4(al, Pl + off);
                }
#pragma unroll
                for (int ntp = 0; ntp < 2; ntp++) {
                    const uint32_t off = SWZ((ks * 16 + (lsub & 1) * 8 + lrow) * 128
                                             + (nloc + ntp * 16 + (lsub >> 1) * 8) * 2);
                    uint32_t bh[4], bl[4];
                    ldm_x4t(bh, Vh + off);
                    ldm_x4t(bl, Vl + off);
#pragma unroll
                    for (int t = 0; t < 2; t++) {
                        mma_bf16(acc2[ntp * 2 + t], ah, bh + t * 2);
                        mma_bf16(acc2[ntp * 2 + t], ah, bl + t * 2);
                        mma_bf16(acc2[ntp * 2 + t], al, bh + t * 2);
                    }
                }
            }
            __syncthreads();
        }

        {
            const int r0 = q0 + wm + grp;
#pragma unroll
            for (int nt = 0; nt < 4; nt++) {
                const int col = dc * 128 + wn2 + nt * 8 + qd * 2;
                *(float2*)&out[((size_t)b * SS + r0) * UU + col] =
                    make_float2(acc2[nt][0], acc2[nt][1]);
                *(float2*)&out[((size_t)b * SS + r0 + 8) * UU + col] =
                    make_float2(acc2[nt][2], acc2[nt][3]);
            }
        }
    }
}

// ---------------------------------------------------------------------------
extern "C" void kernel_launch(void* const* d_in, const int* in_sizes, int n_in,
                              void* d_out, int out_size)
{
    const float* x  = (const float*)d_in[0];
    const float* Wq = (const float*)d_in[1];
    const float* Wk = (const float*)d_in[2];
    const float* Wv = (const float*)d_in[3];
    const float* bq = (const float*)d_in[4];
    const float* bk = (const float*)d_in[5];
    const float* bv = (const float*)d_in[6];
    float* out = (float*)d_out;

    cudaFuncSetAttribute(qkv_tc,
                         cudaFuncAttributeMaxDynamicSharedMemorySize, GEMM_SMEM);
    cudaFuncSetAttribute(attn_fused,
                         cudaFuncAttributeMaxDynamicSharedMemorySize, FA_SMEM);

    prep_x<<<(BB * SS * DD / 4) / 256, 256>>>(x);
    prep_w<<<dim3(UU / 32, DD / 32, 3), 256>>>(Wq, Wk, Wv);
    qkv_tc<<<dim3(UU / 128, BB * SS / 128, 3), 512, GEMM_SMEM>>>(bq, bk, bv);
    attn_fused<<<dim3(NT2, BB), 512, FA_SMEM>>>(out);
}

// round 8
// speedup vs baseline: 1.4909x; 1.4909x over previous
#include <cuda_runtime.h>
#include <cuda_fp16.h>
#include <cstdint>

#define BB 8
#define SS 2048
#define DD 512
#define UU 512
#define QT2 64
#define NT2 (SS/QT2)
#define WIN2 320
#define SCALE 0.044194173824159216f

// ---------------------------------------------------------------------------
// Scratch (fp16)
// ---------------------------------------------------------------------------
__device__ __half g_xh[(size_t)BB * SS * DD];      // x, plain fp16 (1-pass qkv)
__device__ __half g_wth[3ull * UU * DD];           // W transposed [w][n][k], fp16
__device__ __half g_qh[(size_t)BB * SS * UU];
__device__ __half g_ql[(size_t)BB * SS * UU];
__device__ __half g_kh[(size_t)BB * SS * UU];
__device__ __half g_kl[(size_t)BB * SS * UU];
__device__ __half g_vh[(size_t)BB * SS * UU];
__device__ __half g_vl[(size_t)BB * SS * UU];

// ---------------------------------------------------------------------------
// Helpers (baseline PTX only — valid under compute_103)
// ---------------------------------------------------------------------------
__device__ __forceinline__ uint32_t smem_u32(const void* p) {
    uint32_t a;
    asm("{ .reg .u64 t; cvta.to.shared.u64 t, %1; cvt.u32.u64 %0, t; }"
        : "=r"(a) : "l"(p));
    return a;
}
#define SWZ(o) ((o) ^ (((o) >> 3) & 0x70))

__device__ __forceinline__ void cp16(uint32_t s, const void* g) {
    asm volatile("cp.async.cg.shared.global [%0], [%1], 16;" :: "r"(s), "l"(g));
}
#define CP_COMMIT() asm volatile("cp.async.commit_group;" ::: "memory")
#define CP_WAIT(n)  asm volatile("cp.async.wait_group %0;" :: "n"(n) : "memory")

__device__ __forceinline__ void ldm_x4(uint32_t* r, uint32_t a) {
    asm volatile("ldmatrix.sync.aligned.m8n8.x4.shared.b16 {%0,%1,%2,%3}, [%4];"
        : "=r"(r[0]), "=r"(r[1]), "=r"(r[2]), "=r"(r[3]) : "r"(a));
}
__device__ __forceinline__ void ldm_x4t(uint32_t* r, uint32_t a) {
    asm volatile("ldmatrix.sync.aligned.m8n8.x4.trans.shared.b16 {%0,%1,%2,%3}, [%4];"
        : "=r"(r[0]), "=r"(r[1]), "=r"(r[2]), "=r"(r[3]) : "r"(a));
}
__device__ __forceinline__ void mma_f16(float* d, const uint32_t* a, const uint32_t* b) {
    asm volatile("mma.sync.aligned.m16n8k16.row.col.f32.f16.f16.f32 "
        "{%0,%1,%2,%3}, {%4,%5,%6,%7}, {%8,%9}, {%0,%1,%2,%3};"
        : "+f"(d[0]), "+f"(d[1]), "+f"(d[2]), "+f"(d[3])
        : "r"(a[0]), "r"(a[1]), "r"(a[2]), "r"(a[3]), "r"(b[0]), "r"(b[1]));
}
__device__ __forceinline__ int iclamp(int v, int lo, int hi) {
    return v < lo ? lo : (v > hi ? hi : v);
}

// ---------------------------------------------------------------------------
// Prep: fp32 -> fp16 x
// ---------------------------------------------------------------------------
__global__ __launch_bounds__(256) void prep_x(const float* __restrict__ x)
{
    const size_t i4 = (size_t)blockIdx.x * 256 + threadIdx.x;
    float4 v = ((const float4*)x)[i4];
    __half2* oh = (__half2*)g_xh;
    oh[i4 * 2]     = __half2(__float2half_rn(v.x), __float2half_rn(v.y));
    oh[i4 * 2 + 1] = __half2(__float2half_rn(v.z), __float2half_rn(v.w));
}

// ---------------------------------------------------------------------------
// Prep: transpose W[k][n] -> Wt[n][k], fp16
// ---------------------------------------------------------------------------
__global__ __launch_bounds__(256) void prep_w(
    const float* __restrict__ Wq, const float* __restrict__ Wk, const float* __restrict__ Wv)
{
    __shared__ float t[32][33];
    const int w = blockIdx.z;
    const float* __restrict__ W = (w == 0) ? Wq : (w == 1) ? Wk : Wv;
    const int n0 = blockIdx.x * 32;
    const int k0 = blockIdx.y * 32;
    const int tx = threadIdx.x & 31;
    const int ty = threadIdx.x >> 5;
#pragma unroll
    for (int i = 0; i < 4; i++) {
        const int r = ty + i * 8;
        t[r][tx] = W[(size_t)(k0 + r) * UU + n0 + tx];
    }
    __syncthreads();
    const size_t base = (size_t)w * UU * DD;
#pragma unroll
    for (int i = 0; i < 4; i++) {
        const int r = ty + i * 8;
        g_wth[base + (size_t)(n0 + r) * DD + k0 + tx] = __float2half_rn(t[tx][r]);
    }
}

// ---------------------------------------------------------------------------
// QKV GEMM: 1-pass fp16. CTA 128x128, 8 warps of 32x64 tiles, K=512 in
// 8 chunks of 64, 2-stage cp.async. grid (4, 128, 3), 256 threads, 64 KB smem.
// Epilogue: fp32 acc + bias -> fp16 hi/lo for the 3-pass attention.
// ---------------------------------------------------------------------------
#define Q_A 0
#define Q_B 16384
#define Q_BUF 32768
#define GEMM_SMEM (2 * Q_BUF)

__global__ __launch_bounds__(256, 1) void qkv_tc(
    const float* __restrict__ bq, const float* __restrict__ bk, const float* __restrict__ bv)
{
    extern __shared__ char sm[];
    const uint32_t sbase = smem_u32(sm);
    const int tid  = threadIdx.x;
    const int warp = tid >> 5;
    const int lane = tid & 31;
    const int w3 = blockIdx.z;
    const int n0 = blockIdx.x * 128;
    const int m0 = blockIdx.y * 128;

    const int wm = (warp & 3) * 32;
    const int wn = (warp >> 2) * 64;

    const __half* __restrict__ xh = g_xh + (size_t)m0 * DD;
    const __half* __restrict__ wh = g_wth + (size_t)w3 * UU * DD + (size_t)n0 * DD;

    auto issue_chunk = [&](int c, int buf) {
        const int kc0 = c * 64;
        const uint32_t bs = sbase + buf * Q_BUF;
#pragma unroll
        for (int i = 0; i < 4; i++) {
            const int f = tid + i * 256;
            const int row = f >> 3, seg = (f & 7) * 16;
            const uint32_t so = SWZ(row * 128 + seg);
            cp16(bs + Q_A + so, (const char*)(xh + (size_t)row * DD + kc0) + seg);
            cp16(bs + Q_B + so, (const char*)(wh + (size_t)row * DD + kc0) + seg);
        }
        CP_COMMIT();
    };

    float acc[2][8][4];
#pragma unroll
    for (int mt = 0; mt < 2; mt++)
#pragma unroll
        for (int nt = 0; nt < 8; nt++)
#pragma unroll
            for (int i = 0; i < 4; i++) acc[mt][nt][i] = 0.f;

    issue_chunk(0, 0);

    const int lsub = lane >> 3;
    const int lrow = lane & 7;
    const int a_ro = (lsub & 1) * 8;
    const int a_ko = (lsub >> 1) * 16;
    const int b_ro = (lsub >> 1) * 8;
    const int b_ko = (lsub & 1) * 16;

    for (int c = 0; c < 8; c++) {
        if (c < 7) { issue_chunk(c + 1, (c + 1) & 1); CP_WAIT(1); }
        else       { CP_WAIT(0); }
        __syncthreads();

        const uint32_t bs = sbase + (c & 1) * Q_BUF;

#pragma unroll
        for (int ks = 0; ks < 4; ks++) {
            const int kb = ks * 32;
            uint32_t ah[2][4];
#pragma unroll
            for (int mt = 0; mt < 2; mt++) {
                const uint32_t off = SWZ((wm + mt * 16 + lrow + a_ro) * 128 + kb + a_ko);
                ldm_x4(ah[mt], bs + Q_A + off);
            }
#pragma unroll
            for (int ntp = 0; ntp < 4; ntp++) {
                const uint32_t off = SWZ((wn + ntp * 16 + b_ro + lrow) * 128 + kb + b_ko);
                uint32_t bh[4];
                ldm_x4(bh, bs + Q_B + off);
#pragma unroll
                for (int t = 0; t < 2; t++)
#pragma unroll
                    for (int mt = 0; mt < 2; mt++)
                        mma_f16(acc[mt][ntp * 2 + t], ah[mt], bh + t * 2);
            }
        }
        __syncthreads();
    }

    // Epilogue: +bias, hi/lo split, store fp16
    const float* __restrict__ bias = (w3 == 0) ? bq : (w3 == 1) ? bk : bv;
    __half* __restrict__ oh = (w3 == 0) ? g_qh : (w3 == 1) ? g_kh : g_vh;
    __half* __restrict__ ol = (w3 == 0) ? g_ql : (w3 == 1) ? g_kl : g_vl;
    const int grp = lane >> 2;
    const int qd  = lane & 3;
#pragma unroll
    for (int nt = 0; nt < 8; nt++) {
        const int col = n0 + wn + nt * 8 + qd * 2;
        const float b0 = bias[col], b1 = bias[col + 1];
#pragma unroll
        for (int mt = 0; mt < 2; mt++) {
            const int r0 = m0 + wm + mt * 16 + grp;
            const float f0 = acc[mt][nt][0] + b0, f1 = acc[mt][nt][1] + b1;
            const float f2 = acc[mt][nt][2] + b0, f3 = acc[mt][nt][3] + b1;
            __half h0 = __float2half_rn(f0), h1 = __float2half_rn(f1);
            __half h2 = __float2half_rn(f2), h3 = __float2half_rn(f3);
            *(__half2*)&oh[(size_t)r0 * UU + col] = __half2(h0, h1);
            *(__half2*)&ol[(size_t)r0 * UU + col] = __half2(
                __float2half_rn(f0 - __half2float(h0)),
                __float2half_rn(f1 - __half2float(h1)));
            *(__half2*)&oh[(size_t)(r0 + 8) * UU + col] = __half2(h2, h3);
            *(__half2*)&ol[(size_t)(r0 + 8) * UU + col] = __half2(
                __float2half_rn(f2 - __half2float(h2)),
                __float2half_rn(f3 - __half2float(h3)));
        }
    }
}

// ---------------------------------------------------------------------------
// Fused attention (fp16 3-pass hi/lo): scores + masked softmax + P V,
// P kept in SMEM. grid (32, 8), 256 threads, 225 KB smem.
// ---------------------------------------------------------------------------
#define FA_AH 0
#define FA_AL 8192
#define FA_BH 16384
#define FA_BL 57344
#define FA_BUF 98304
#define SSTR 321
#define P_OFF 82944
#define V_OFF 164864
#define FA_SMEM 230400

__global__ __launch_bounds__(256, 1) void attn_fused(float* __restrict__ out)
{
    extern __shared__ char sm[];
    const uint32_t sbase = smem_u32(sm);
    const int tid  = threadIdx.x;
    const int warp = tid >> 5;
    const int lane = tid & 31;
    const int b  = blockIdx.y;
    const int q0 = blockIdx.x * QT2;
    const int kstart = q0 - 128;

    const __half* __restrict__ qh = g_qh + (size_t)(b * SS + q0) * UU;
    const __half* __restrict__ ql = g_ql + (size_t)(b * SS + q0) * UU;
    const __half* __restrict__ kh = g_kh + (size_t)b * SS * UU;
    const __half* __restrict__ kl = g_kl + (size_t)b * SS * UU;
    const __half* __restrict__ vh = g_vh + (size_t)b * SS * UU;
    const __half* __restrict__ vl = g_vl + (size_t)b * SS * UU;

    const int lsub = lane >> 3;
    const int lrow = lane & 7;
    const int a_ro = (lsub & 1) * 8;
    const int a_ko = (lsub >> 1) * 16;
    const int b_ro = (lsub >> 1) * 8;
    const int b_ko = (lsub & 1) * 16;

    // ---------------- Phase 1: S = Q K^T ----------------
    auto issueK = [&](int c, int buf) {
        const int kc0 = c * 64;
        const uint32_t bs = sbase + buf * FA_BUF;
#pragma unroll
        for (int i = 0; i < 2; i++) {
            const int f = tid + i * 256;
            const int row = f >> 3, seg = (f & 7) * 16;
            const uint32_t so = SWZ(row * 128 + seg);
            cp16(bs + FA_AH + so, (const char*)(qh + (size_t)row * UU + kc0) + seg);
            cp16(bs + FA_AL + so, (const char*)(ql + (size_t)row * UU + kc0) + seg);
        }
#pragma unroll
        for (int i = 0; i < 10; i++) {
            const int f = tid + i * 256;
            const int row = f >> 3, seg = (f & 7) * 16;
            const int j = iclamp(kstart + row, 0, SS - 1);
            const uint32_t so = SWZ(row * 128 + seg);
            cp16(bs + FA_BH + so, (const char*)(kh + (size_t)j * UU + kc0) + seg);
            cp16(bs + FA_BL + so, (const char*)(kl + (size_t)j * UU + kc0) + seg);
        }
        CP_COMMIT();
    };

    float acc[2][10][4];
#pragma unroll
    for (int mt = 0; mt < 2; mt++)
#pragma unroll
        for (int nt = 0; nt < 10; nt++)
#pragma unroll
            for (int i = 0; i < 4; i++) acc[mt][nt][i] = 0.f;

    issueK(0, 0);

    const int wm = (warp & 1) * 32;
    const int wn = (warp >> 1) * 80;

    for (int c = 0; c < 8; c++) {
        if (c < 7) { issueK(c + 1, (c + 1) & 1); CP_WAIT(1); }
        else       { CP_WAIT(0); }
        __syncthreads();

        const uint32_t bs = sbase + (c & 1) * FA_BUF;
#pragma unroll
        for (int ks = 0; ks < 4; ks++) {
            const int kb = ks * 32;
            uint32_t ah[2][4], al[2][4];
#pragma unroll
            for (int mt = 0; mt < 2; mt++) {
                const uint32_t off = SWZ((wm + mt * 16 + lrow + a_ro) * 128 + kb + a_ko);
                ldm_x4(ah[mt], bs + FA_AH + off);
                ldm_x4(al[mt], bs + FA_AL + off);
            }
#pragma unroll
            for (int ntp = 0; ntp < 5; ntp++) {
                const uint32_t off = SWZ((wn + ntp * 16 + b_ro + lrow) * 128 + kb + b_ko);
                uint32_t bh[4], bl[4];
                ldm_x4(bh, bs + FA_BH + off);
                ldm_x4(bl, bs + FA_BL + off);
#pragma unroll
                for (int t = 0; t < 2; t++) {
#pragma unroll
                    for (int mt = 0; mt < 2; mt++) {
                        mma_f16(acc[mt][ntp * 2 + t], ah[mt], bh + t * 2);
                        mma_f16(acc[mt][ntp * 2 + t], ah[mt], bl + t * 2);
                        mma_f16(acc[mt][ntp * 2 + t], al[mt], bh + t * 2);
                    }
                }
            }
        }
        __syncthreads();
    }

    // ---------------- V prefetch (overlaps softmax) ----------------
    auto issueV = [&](int dc, int kc, int vbuf) {
        const uint32_t bs = sbase + V_OFF + vbuf * 32768;
        const int d0 = dc * 128;
#pragma unroll
        for (int i = 0; i < 2; i++) {
            const int f = tid + i * 256;
            const int row = f >> 3, seg = (f & 7) * 16;
            const int j = iclamp(kstart + kc * 64 + row, 0, SS - 1);
            const uint32_t so = SWZ(row * 128 + seg);
            cp16(bs + 0     + so, (const char*)(vh + (size_t)j * UU + d0) + seg);
            cp16(bs + 8192  + so, (const char*)(vl + (size_t)j * UU + d0) + seg);
            cp16(bs + 16384 + so, (const char*)(vh + (size_t)j * UU + d0 + 64) + seg);
            cp16(bs + 24576 + so, (const char*)(vl + (size_t)j * UU + d0 + 64) + seg);
        }
        CP_COMMIT();
    };
    issueV(0, 0, 0);

    // ---------------- S -> smem, masked softmax, P -> smem ----------------
    float* Ss = (float*)sm;
    const int grp = lane >> 2;
    const int qd  = lane & 3;
#pragma unroll
    for (int mt = 0; mt < 2; mt++) {
        const int r0 = wm + mt * 16 + grp;
#pragma unroll
        for (int nt = 0; nt < 10; nt++) {
            const int col = wn + nt * 8 + qd * 2;
            Ss[r0 * SSTR + col]           = acc[mt][nt][0] * SCALE;
            Ss[r0 * SSTR + col + 1]       = acc[mt][nt][1] * SCALE;
            Ss[(r0 + 8) * SSTR + col]     = acc[mt][nt][2] * SCALE;
            Ss[(r0 + 8) * SSTR + col + 1] = acc[mt][nt][3] * SCALE;
        }
    }
    __syncthreads();

#pragma unroll
    for (int r8 = 0; r8 < 8; r8++) {
        const int rr = warp * 8 + r8;
        const int cmin = (rr > -kstart) ? rr : -kstart;
        int cmax = rr + 256;
        const int chi = SS - 1 - kstart;
        if (chi < cmax) cmax = chi;

        float mx = -1e30f;
        for (int c = lane; c < WIN2; c += 32)
            if (c >= cmin && c <= cmax) mx = fmaxf(mx, Ss[rr * SSTR + c]);
#pragma unroll
        for (int off = 16; off > 0; off >>= 1)
            mx = fmaxf(mx, __shfl_xor_sync(0xFFFFFFFFu, mx, off));

        float sum = 0.f;
        for (int c = lane; c < WIN2; c += 32) {
            float e = 0.f;
            if (c >= cmin && c <= cmax) e = __expf(Ss[rr * SSTR + c] - mx);
            Ss[rr * SSTR + c] = e;
            sum += e;
        }
#pragma unroll
        for (int off = 16; off > 0; off >>= 1)
            sum += __shfl_xor_sync(0xFFFFFFFFu, sum, off);

        const float inv = 1.0f / sum;
        for (int c = lane; c < WIN2; c += 32) {
            const float p = Ss[rr * SSTR + c] * inv;
            const __half h = __float2half_rn(p);
            const uint32_t pb = P_OFF + (c >> 6) * 16384 + SWZ(rr * 128 + (c & 63) * 2);
            *(__half*)(sm + pb)        = h;
            *(__half*)(sm + pb + 8192) = __float2half_rn(p - __half2float(h));
        }
    }
    __syncthreads();

    // ---------------- Phase 2: out = P V ----------------
    const int wn2  = (warp >> 1) * 32;
    const int sub  = wn2 >> 6;
    const int nloc = wn2 & 63;

    for (int dc = 0; dc < 4; dc++) {
        float acc2[2][4][4];
#pragma unroll
        for (int mt = 0; mt < 2; mt++)
#pragma unroll
            for (int nt = 0; nt < 4; nt++)
#pragma unroll
                for (int i = 0; i < 4; i++) acc2[mt][nt][i] = 0.f;

        for (int kc = 0; kc < 5; kc++) {
            const int it = dc * 5 + kc;
            if (it < 19) {
                const int nit = it + 1;
                issueV(nit / 5, nit % 5, nit & 1);
                CP_WAIT(1);
            } else {
                CP_WAIT(0);
            }
            __syncthreads();

            const uint32_t vb = sbase + V_OFF + (it & 1) * 32768;
            const uint32_t Vh = vb + sub * 16384;
            const uint32_t Vl = Vh + 8192;
            const uint32_t Ph = sbase + P_OFF + kc * 16384;
            const uint32_t Pl = Ph + 8192;

#pragma unroll
            for (int ks = 0; ks < 4; ks++) {
                uint32_t ah[2][4], al[2][4];
#pragma unroll
                for (int mt = 0; mt < 2; mt++) {
                    const uint32_t off = SWZ((wm + mt * 16 + lrow + a_ro) * 128 + ks * 32 + a_ko);
                    ldm_x4(ah[mt], Ph + off);
                    ldm_x4(al[mt], Pl + off);
                }
#pragma unroll
                for (int ntp = 0; ntp < 2; ntp++) {
                    const uint32_t off = SWZ((ks * 16 + (lsub & 1) * 8 + lrow) * 128
                                             + (nloc + ntp * 16 + (lsub >> 1) * 8) * 2);
                    uint32_t bh[4], bl[4];
                    ldm_x4t(bh, Vh + off);
                    ldm_x4t(bl, Vl + off);
#pragma unroll
                    for (int t = 0; t < 2; t++) {
#pragma unroll
                        for (int mt = 0; mt < 2; mt++) {
                            mma_f16(acc2[mt][ntp * 2 + t], ah[mt], bh + t * 2);
                            mma_f16(acc2[mt][ntp * 2 + t], ah[mt], bl + t * 2);
                            mma_f16(acc2[mt][ntp * 2 + t], al[mt], bh + t * 2);
                        }
                    }
                }
            }
            __syncthreads();
        }

#pragma unroll
        for (int mt = 0; mt < 2; mt++) {
            const int r0 = q0 + wm + mt * 16 + grp;
#pragma unroll
            for (int nt = 0; nt < 4; nt++) {
                const int col = dc * 128 + wn2 + nt * 8 + qd * 2;
                *(float2*)&out[((size_t)b * SS + r0) * UU + col] =
                    make_float2(acc2[mt][nt][0], acc2[mt][nt][1]);
                *(float2*)&out[((size_t)b * SS + r0 + 8) * UU + col] =
                    make_float2(acc2[mt][nt][2], acc2[mt][nt][3]);
            }
        }
    }
}

// ---------------------------------------------------------------------------
extern "C" void kernel_launch(void* const* d_in, const int* in_sizes, int n_in,
                              void* d_out, int out_size)
{
    const float* x  = (const float*)d_in[0];
    const float* Wq = (const float*)d_in[1];
    const float* Wk = (const float*)d_in[2];
    const float* Wv = (const float*)d_in[3];
    const float* bq = (const float*)d_in[4];
    const float* bk = (const float*)d_in[5];
    const float* bv = (const float*)d_in[6];
    float* out = (float*)d_out;

    cudaFuncSetAttribute(qkv_tc,
                         cudaFuncAttributeMaxDynamicSharedMemorySize, GEMM_SMEM);
    cudaFuncSetAttribute(attn_fused,
                         cudaFuncAttributeMaxDynamicSharedMemorySize, FA_SMEM);

    prep_x<<<(BB * SS * DD / 4) / 256, 256>>>(x);
    prep_w<<<dim3(UU / 32, DD / 32, 3), 256>>>(Wq, Wk, Wv);
    qkv_tc<<<dim3(UU / 128, BB * SS / 128, 3), 256, GEMM_SMEM>>>(bq, bk, bv);
    attn_fused<<<dim3(NT2, BB), 256, FA_SMEM>>>(out);
}

// round 9
// speedup vs baseline: 2.4249x; 1.6265x over previous
#include <cuda_runtime.h>
#include <cuda_fp16.h>
#include <cstdint>

#define BB 8
#define SS 2048
#define DD 512
#define UU 512
#define QT2 64
#define NT2 (SS/QT2)
#define WIN2 320
#define SCALE 0.044194173824159216f

// ---------------------------------------------------------------------------
// Scratch (fp16, single precision level everywhere now)
// ---------------------------------------------------------------------------
__device__ __half g_xh[(size_t)BB * SS * DD];
__device__ __half g_wth[3ull * UU * DD];           // W transposed [w][n][k]
__device__ __half g_q[(size_t)BB * SS * UU];
__device__ __half g_k[(size_t)BB * SS * UU];
__device__ __half g_v[(size_t)BB * SS * UU];

// ---------------------------------------------------------------------------
// Helpers (baseline PTX only — valid under compute_103)
// ---------------------------------------------------------------------------
__device__ __forceinline__ uint32_t smem_u32(const void* p) {
    uint32_t a;
    asm("{ .reg .u64 t; cvta.to.shared.u64 t, %1; cvt.u32.u64 %0, t; }"
        : "=r"(a) : "l"(p));
    return a;
}
#define SWZ(o) ((o) ^ (((o) >> 3) & 0x70))

__device__ __forceinline__ void cp16(uint32_t s, const void* g) {
    asm volatile("cp.async.cg.shared.global [%0], [%1], 16;" :: "r"(s), "l"(g));
}
#define CP_COMMIT() asm volatile("cp.async.commit_group;" ::: "memory")
#define CP_WAIT(n)  asm volatile("cp.async.wait_group %0;" :: "n"(n) : "memory")

__device__ __forceinline__ void ldm_x4(uint32_t* r, uint32_t a) {
    asm volatile("ldmatrix.sync.aligned.m8n8.x4.shared.b16 {%0,%1,%2,%3}, [%4];"
        : "=r"(r[0]), "=r"(r[1]), "=r"(r[2]), "=r"(r[3]) : "r"(a));
}
__device__ __forceinline__ void ldm_x4t(uint32_t* r, uint32_t a) {
    asm volatile("ldmatrix.sync.aligned.m8n8.x4.trans.shared.b16 {%0,%1,%2,%3}, [%4];"
        : "=r"(r[0]), "=r"(r[1]), "=r"(r[2]), "=r"(r[3]) : "r"(a));
}
__device__ __forceinline__ void mma_f16(float* d, const uint32_t* a, const uint32_t* b) {
    asm volatile("mma.sync.aligned.m16n8k16.row.col.f32.f16.f16.f32 "
        "{%0,%1,%2,%3}, {%4,%5,%6,%7}, {%8,%9}, {%0,%1,%2,%3};"
        : "+f"(d[0]), "+f"(d[1]), "+f"(d[2]), "+f"(d[3])
        : "r"(a[0]), "r"(a[1]), "r"(a[2]), "r"(a[3]), "r"(b[0]), "r"(b[1]));
}
__device__ __forceinline__ int iclamp(int v, int lo, int hi) {
    return v < lo ? lo : (v > hi ? hi : v);
}

// ---------------------------------------------------------------------------
// Prep: fp32 -> fp16 x
// ---------------------------------------------------------------------------
__global__ __launch_bounds__(256) void prep_x(const float* __restrict__ x)
{
    const size_t i4 = (size_t)blockIdx.x * 256 + threadIdx.x;
    float4 v = ((const float4*)x)[i4];
    __half2* oh = (__half2*)g_xh;
    oh[i4 * 2]     = __half2(__float2half_rn(v.x), __float2half_rn(v.y));
    oh[i4 * 2 + 1] = __half2(__float2half_rn(v.z), __float2half_rn(v.w));
}

// ---------------------------------------------------------------------------
// Prep: transpose W[k][n] -> Wt[n][k], fp16
// ---------------------------------------------------------------------------
__global__ __launch_bounds__(256) void prep_w(
    const float* __restrict__ Wq, const float* __restrict__ Wk, const float* __restrict__ Wv)
{
    __shared__ float t[32][33];
    const int w = blockIdx.z;
    const float* __restrict__ W = (w == 0) ? Wq : (w == 1) ? Wk : Wv;
    const int n0 = blockIdx.x * 32;
    const int k0 = blockIdx.y * 32;
    const int tx = threadIdx.x & 31;
    const int ty = threadIdx.x >> 5;
#pragma unroll
    for (int i = 0; i < 4; i++) {
        const int r = ty + i * 8;
        t[r][tx] = W[(size_t)(k0 + r) * UU + n0 + tx];
    }
    __syncthreads();
    const size_t base = (size_t)w * UU * DD;
#pragma unroll
    for (int i = 0; i < 4; i++) {
        const int r = ty + i * 8;
        g_wth[base + (size_t)(n0 + r) * DD + k0 + tx] = __float2half_rn(t[tx][r]);
    }
}

// ---------------------------------------------------------------------------
// QKV GEMM: 1-pass fp16. CTA 128x128, 8 warps of 32x64 tiles, K=512 in
// 8 chunks of 64, 2-stage cp.async. 2 CTAs/SM. grid (4, 128, 3), 256 thr.
// ---------------------------------------------------------------------------
#define Q_A 0
#define Q_B 16384
#define Q_BUF 32768
#define GEMM_SMEM (2 * Q_BUF)

__global__ __launch_bounds__(256, 2) void qkv_tc(
    const float* __restrict__ bq, const float* __restrict__ bk, const float* __restrict__ bv)
{
    extern __shared__ char sm[];
    const uint32_t sbase = smem_u32(sm);
    const int tid  = threadIdx.x;
    const int warp = tid >> 5;
    const int lane = tid & 31;
    const int w3 = blockIdx.z;
    const int n0 = blockIdx.x * 128;
    const int m0 = blockIdx.y * 128;

    const int wm = (warp & 3) * 32;
    const int wn = (warp >> 2) * 64;

    const __half* __restrict__ xh = g_xh + (size_t)m0 * DD;
    const __half* __restrict__ wh = g_wth + (size_t)w3 * UU * DD + (size_t)n0 * DD;

    auto issue_chunk = [&](int c, int buf) {
        const int kc0 = c * 64;
        const uint32_t bs = sbase + buf * Q_BUF;
#pragma unroll
        for (int i = 0; i < 4; i++) {
            const int f = tid + i * 256;
            const int row = f >> 3, seg = (f & 7) * 16;
            const uint32_t so = SWZ(row * 128 + seg);
            cp16(bs + Q_A + so, (const char*)(xh + (size_t)row * DD + kc0) + seg);
            cp16(bs + Q_B + so, (const char*)(wh + (size_t)row * DD + kc0) + seg);
        }
        CP_COMMIT();
    };

    float acc[2][8][4];
#pragma unroll
    for (int mt = 0; mt < 2; mt++)
#pragma unroll
        for (int nt = 0; nt < 8; nt++)
#pragma unroll
            for (int i = 0; i < 4; i++) acc[mt][nt][i] = 0.f;

    issue_chunk(0, 0);

    const int lsub = lane >> 3;
    const int lrow = lane & 7;
    const int a_ro = (lsub & 1) * 8;
    const int a_ko = (lsub >> 1) * 16;
    const int b_ro = (lsub >> 1) * 8;
    const int b_ko = (lsub & 1) * 16;

    for (int c = 0; c < 8; c++) {
        if (c < 7) { issue_chunk(c + 1, (c + 1) & 1); CP_WAIT(1); }
        else       { CP_WAIT(0); }
        __syncthreads();

        const uint32_t bs = sbase + (c & 1) * Q_BUF;

#pragma unroll
        for (int ks = 0; ks < 4; ks++) {
            const int kb = ks * 32;
            uint32_t ah[2][4];
#pragma unroll
            for (int mt = 0; mt < 2; mt++) {
                const uint32_t off = SWZ((wm + mt * 16 + lrow + a_ro) * 128 + kb + a_ko);
                ldm_x4(ah[mt], bs + Q_A + off);
            }
#pragma unroll
            for (int ntp = 0; ntp < 4; ntp++) {
                const uint32_t off = SWZ((wn + ntp * 16 + b_ro + lrow) * 128 + kb + b_ko);
                uint32_t bh[4];
                ldm_x4(bh, bs + Q_B + off);
#pragma unroll
                for (int t = 0; t < 2; t++)
#pragma unroll
                    for (int mt = 0; mt < 2; mt++)
                        mma_f16(acc[mt][ntp * 2 + t], ah[mt], bh + t * 2);
            }
        }
        __syncthreads();
    }

    // Epilogue: +bias, store fp16
    const float* __restrict__ bias = (w3 == 0) ? bq : (w3 == 1) ? bk : bv;
    __half* __restrict__ oh = (w3 == 0) ? g_q : (w3 == 1) ? g_k : g_v;
    const int grp = lane >> 2;
    const int qd  = lane & 3;
#pragma unroll
    for (int nt = 0; nt < 8; nt++) {
        const int col = n0 + wn + nt * 8 + qd * 2;
        const float b0 = bias[col], b1 = bias[col + 1];
#pragma unroll
        for (int mt = 0; mt < 2; mt++) {
            const int r0 = m0 + wm + mt * 16 + grp;
            *(__half2*)&oh[(size_t)r0 * UU + col] = __half2(
                __float2half_rn(acc[mt][nt][0] + b0),
                __float2half_rn(acc[mt][nt][1] + b1));
            *(__half2*)&oh[(size_t)(r0 + 8) * UU + col] = __half2(
                __float2half_rn(acc[mt][nt][2] + b0),
                __float2half_rn(acc[mt][nt][3] + b1));
        }
    }
}

// ---------------------------------------------------------------------------
// Fused attention, 1-pass fp16: S = Q K^T, masked softmax, out = P V.
// P kept in SMEM (fp16). grid (32, 8), 256 threads, 168 KB smem.
// ---------------------------------------------------------------------------
#define FA_A 0
#define FA_B 8192
#define FA_BUF 49152              // Q 8KB + K 40KB
#define SSTR 321
#define P_OFF 98304               // after both FA buffers; 5 x 8KB
#define V_OFF 139264              // 2 x 16KB double buffer
#define FA_SMEM 172032

__global__ __launch_bounds__(256, 1) void attn_fused(float* __restrict__ out)
{
    extern __shared__ char sm[];
    const uint32_t sbase = smem_u32(sm);
    const int tid  = threadIdx.x;
    const int warp = tid >> 5;
    const int lane = tid & 31;
    const int b  = blockIdx.y;
    const int q0 = blockIdx.x * QT2;
    const int kstart = q0 - 128;

    const __half* __restrict__ qp = g_q + (size_t)(b * SS + q0) * UU;
    const __half* __restrict__ kp = g_k + (size_t)b * SS * UU;
    const __half* __restrict__ vp = g_v + (size_t)b * SS * UU;

    const int lsub = lane >> 3;
    const int lrow = lane & 7;
    const int a_ro = (lsub & 1) * 8;
    const int a_ko = (lsub >> 1) * 16;
    const int b_ro = (lsub >> 1) * 8;
    const int b_ko = (lsub & 1) * 16;

    // ---------------- Phase 1: S = Q K^T ----------------
    auto issueK = [&](int c, int buf) {
        const int kc0 = c * 64;
        const uint32_t bs = sbase + buf * FA_BUF;
#pragma unroll
        for (int i = 0; i < 2; i++) {            // Q: 512 chunks
            const int f = tid + i * 256;
            const int row = f >> 3, seg = (f & 7) * 16;
            const uint32_t so = SWZ(row * 128 + seg);
            cp16(bs + FA_A + so, (const char*)(qp + (size_t)row * UU + kc0) + seg);
        }
#pragma unroll
        for (int i = 0; i < 10; i++) {           // K: 2560 chunks
            const int f = tid + i * 256;
            const int row = f >> 3, seg = (f & 7) * 16;
            const int j = iclamp(kstart + row, 0, SS - 1);
            const uint32_t so = SWZ(row * 128 + seg);
            cp16(bs + FA_B + so, (const char*)(kp + (size_t)j * UU + kc0) + seg);
        }
        CP_COMMIT();
    };

    float acc[2][10][4];
#pragma unroll
    for (int mt = 0; mt < 2; mt++)
#pragma unroll
        for (int nt = 0; nt < 10; nt++)
#pragma unroll
            for (int i = 0; i < 4; i++) acc[mt][nt][i] = 0.f;

    issueK(0, 0);

    const int wm = (warp & 1) * 32;
    const int wn = (warp >> 1) * 80;

    for (int c = 0; c < 8; c++) {
        if (c < 7) { issueK(c + 1, (c + 1) & 1); CP_WAIT(1); }
        else       { CP_WAIT(0); }
        __syncthreads();

        const uint32_t bs = sbase + (c & 1) * FA_BUF;
#pragma unroll
        for (int ks = 0; ks < 4; ks++) {
            const int kb = ks * 32;
            uint32_t ah[2][4];
#pragma unroll
            for (int mt = 0; mt < 2; mt++) {
                const uint32_t off = SWZ((wm + mt * 16 + lrow + a_ro) * 128 + kb + a_ko);
                ldm_x4(ah[mt], bs + FA_A + off);
            }
#pragma unroll
            for (int ntp = 0; ntp < 5; ntp++) {
                const uint32_t off = SWZ((wn + ntp * 16 + b_ro + lrow) * 128 + kb + b_ko);
                uint32_t bh[4];
                ldm_x4(bh, bs + FA_B + off);
#pragma unroll
                for (int t = 0; t < 2; t++)
#pragma unroll
                    for (int mt = 0; mt < 2; mt++)
                        mma_f16(acc[mt][ntp * 2 + t], ah[mt], bh + t * 2);
            }
        }
        __syncthreads();
    }

    // ---------------- V prefetch (overlaps softmax) ----------------
    auto issueV = [&](int dc, int kc, int vbuf) {
        const uint32_t bs = sbase + V_OFF + vbuf * 16384;
        const int d0 = dc * 128;
#pragma unroll
        for (int i = 0; i < 2; i++) {            // 64 rows x 128B per half
            const int f = tid + i * 256;
            const int row = f >> 3, seg = (f & 7) * 16;
            const int j = iclamp(kstart + kc * 64 + row, 0, SS - 1);
            const uint32_t so = SWZ(row * 128 + seg);
            cp16(bs + 0    + so, (const char*)(vp + (size_t)j * UU + d0) + seg);
            cp16(bs + 8192 + so, (const char*)(vp + (size_t)j * UU + d0 + 64) + seg);
        }
        CP_COMMIT();
    };
    issueV(0, 0, 0);

    // ---------------- S -> smem, masked softmax, P -> smem ----------------
    float* Ss = (float*)sm;
    const int grp = lane >> 2;
    const int qd  = lane & 3;
#pragma unroll
    for (int mt = 0; mt < 2; mt++) {
        const int r0 = wm + mt * 16 + grp;
#pragma unroll
        for (int nt = 0; nt < 10; nt++) {
            const int col = wn + nt * 8 + qd * 2;
            Ss[r0 * SSTR + col]           = acc[mt][nt][0] * SCALE;
            Ss[r0 * SSTR + col + 1]       = acc[mt][nt][1] * SCALE;
            Ss[(r0 + 8) * SSTR + col]     = acc[mt][nt][2] * SCALE;
            Ss[(r0 + 8) * SSTR + col + 1] = acc[mt][nt][3] * SCALE;
        }
    }
    __syncthreads();

#pragma unroll
    for (int r8 = 0; r8 < 8; r8++) {
        const int rr = warp * 8 + r8;
        const int cmin = (rr > -kstart) ? rr : -kstart;
        int cmax = rr + 256;
        const int chi = SS - 1 - kstart;
        if (chi < cmax) cmax = chi;

        float mx = -1e30f;
        for (int c = lane; c < WIN2; c += 32)
            if (c >= cmin && c <= cmax) mx = fmaxf(mx, Ss[rr * SSTR + c]);
#pragma unroll
        for (int off = 16; off > 0; off >>= 1)
            mx = fmaxf(mx, __shfl_xor_sync(0xFFFFFFFFu, mx, off));

        float sum = 0.f;
        for (int c = lane; c < WIN2; c += 32) {
            float e = 0.f;
            if (c >= cmin && c <= cmax) e = __expf(Ss[rr * SSTR + c] - mx);
            Ss[rr * SSTR + c] = e;
            sum += e;
        }
#pragma unroll
        for (int off = 16; off > 0; off >>= 1)
            sum += __shfl_xor_sync(0xFFFFFFFFu, sum, off);

        const float inv = 1.0f / sum;
        for (int c = lane; c < WIN2; c += 32) {
            const float p = Ss[rr * SSTR + c] * inv;
            const uint32_t pb = P_OFF + (c >> 6) * 8192 + SWZ(rr * 128 + (c & 63) * 2);
            *(__half*)(sm + pb) = __float2half_rn(p);
        }
    }
    __syncthreads();

    // ---------------- Phase 2: out = P V ----------------
    const int wn2  = (warp >> 1) * 32;
    const int sub  = wn2 >> 6;
    const int nloc = wn2 & 63;

    for (int dc = 0; dc < 4; dc++) {
        float acc2[2][4][4];
#pragma unroll
        for (int mt = 0; mt < 2; mt++)
#pragma unroll
            for (int nt = 0; nt < 4; nt++)
#pragma unroll
                for (int i = 0; i < 4; i++) acc2[mt][nt][i] = 0.f;

        for (int kc = 0; kc < 5; kc++) {
            const int it = dc * 5 + kc;
            if (it < 19) {
                const int nit = it + 1;
                issueV(nit / 5, nit % 5, nit & 1);
                CP_WAIT(1);
            } else {
                CP_WAIT(0);
            }
            __syncthreads();

            const uint32_t Vh = sbase + V_OFF + (it & 1) * 16384 + sub * 8192;
            const uint32_t Ph = sbase + P_OFF + kc * 8192;

#pragma unroll
            for (int ks = 0; ks < 4; ks++) {
                uint32_t ah[2][4];
#pragma unroll
                for (int mt = 0; mt < 2; mt++) {
                    const uint32_t off = SWZ((wm + mt * 16 + lrow + a_ro) * 128 + ks * 32 + a_ko);
                    ldm_x4(ah[mt], Ph + off);
                }
#pragma unroll
                for (int ntp = 0; ntp < 2; ntp++) {
                    const uint32_t off = SWZ((ks * 16 + (lsub & 1) * 8 + lrow) * 128
                                             + (nloc + ntp * 16 + (lsub >> 1) * 8) * 2);
                    uint32_t bh[4];
                    ldm_x4t(bh, Vh + off);
#pragma unroll
                    for (int t = 0; t < 2; t++)
#pragma unroll
                        for (int mt = 0; mt < 2; mt++)
                            mma_f16(acc2[mt][ntp * 2 + t], ah[mt], bh + t * 2);
                }
            }
            __syncthreads();
        }

#pragma unroll
        for (int mt = 0; mt < 2; mt++) {
            const int r0 = q0 + wm + mt * 16 + grp;
#pragma unroll
            for (int nt = 0; nt < 4; nt++) {
                const int col = dc * 128 + wn2 + nt * 8 + qd * 2;
                *(float2*)&out[((size_t)b * SS + r0) * UU + col] =
                    make_float2(acc2[mt][nt][0], acc2[mt][nt][1]);
                *(float2*)&out[((size_t)b * SS + r0 + 8) * UU + col] =
                    make_float2(acc2[mt][nt][2], acc2[mt][nt][3]);
            }
        }
    }
}

// ---------------------------------------------------------------------------
extern "C" void kernel_launch(void* const* d_in, const int* in_sizes, int n_in,
                              void* d_out, int out_size)
{
    const float* x  = (const float*)d_in[0];
    const float* Wq = (const float*)d_in[1];
    const float* Wk = (const float*)d_in[2];
    const float* Wv = (const float*)d_in[3];
    const float* bq = (const float*)d_in[4];
    const float* bk = (const float*)d_in[5];
    const float* bv = (const float*)d_in[6];
    float* out = (float*)d_out;

    cudaFuncSetAttribute(qkv_tc,
                         cudaFuncAttributeMaxDynamicSharedMemorySize, GEMM_SMEM);
    cudaFuncSetAttribute(attn_fused,
                         cudaFuncAttributeMaxDynamicSharedMemorySize, FA_SMEM);

    prep_x<<<(BB * SS * DD / 4) / 256, 256>>>(x);
    prep_w<<<dim3(UU / 32, DD / 32, 3), 256>>>(Wq, Wk, Wv);
    qkv_tc<<<dim3(UU / 128, BB * SS / 128, 3), 256, GEMM_SMEM>>>(bq, bk, bv);
    attn_fused<<<dim3(NT2, BB), 256, FA_SMEM>>>(out);
}